// round 6
// baseline (speedup 1.0000x reference)
#include <cuda_runtime.h>

#define NN 4096      // nodes
#define NE 4096      // hyperedges
#define NF 128       // features
#define CAP 192      // per-list capacity (max degree ~58 expected)

// ---------------- scratch (static __device__, zero-initialized) ----------
__device__ float g_theta[NN * NF];        // X @ W            (2 MB, L2-resident)
__device__ float g_U[NE * NF];            // De^-1 H^T theta  (2 MB)
__device__ float g_inv_dv[NN];
__device__ float g_inv_de[NE];
__device__ int   g_col_cnt[NE];           // CSC counts: MUST be 0 at k_fused entry.
                                          // Zero at load; k_spmm1 re-zeroes after use.
__device__ int   g_row_cnt[NN];           // CSR counts
__device__ int   g_col_idx[NE * CAP];
__device__ int   g_row_idx[NN * CAP];

// ---------------- K1: fused init + theta + CSR/CSC build -----------------
// blockIdx roles:  [0, NN)            -> build node row b  (DRAM-bound scan of H)
//                  [NN, NN+128)       -> theta tile        (rides under the scan)
//                  [NN+128, NN+144)   -> diag inverses
__global__ void __launch_bounds__(256) k_fused(const float* __restrict__ X,
                                               const float* __restrict__ W,
                                               const float* __restrict__ H,
                                               const float* __restrict__ Dv,
                                               const float* __restrict__ De) {
    __shared__ float Xs[32][NF];          // theta branch (16 KB)
    __shared__ int   s_cnt;               // build branch

    const int b   = blockIdx.x;
    const int tid = threadIdx.x;

    if (b < NN) {
        // ---- build: one node row. FRONT-BATCH all 4 LDG.128 (MLP=4) ----
        const int n = b;
        if (tid == 0) s_cnt = 0;

        const float4* __restrict__ row =
            reinterpret_cast<const float4*>(H + (size_t)n * NE);
        // issue all loads back-to-back before any dependent work
        float4 v0 = row[tid];
        float4 v1 = row[tid + 256];
        float4 v2 = row[tid + 512];
        float4 v3 = row[tid + 768];
        __syncthreads();                  // s_cnt=0 visible (loads already in flight)

        float vals[16] = {v0.x, v0.y, v0.z, v0.w,
                          v1.x, v1.y, v1.z, v1.w,
                          v2.x, v2.y, v2.z, v2.w,
                          v3.x, v3.y, v3.z, v3.w};

        #pragma unroll
        for (int k = 0; k < 4; k++) {
            int cbase = (tid + k * 256) * 4;
            #pragma unroll
            for (int j = 0; j < 4; j++) {
                if (vals[k * 4 + j] != 0.0f) {
                    int e = cbase + j;
                    int p = atomicAdd(&s_cnt, 1);                 // smem (few per CTA)
                    if (p < CAP) g_row_idx[(size_t)n * CAP + p] = e;
                    int q = atomicAdd(&g_col_cnt[e], 1);          // spread over 4096 addrs
                    if (q < CAP) g_col_idx[(size_t)e * CAP + q] = n;
                }
            }
        }
        __syncthreads();
        if (tid == 0) g_row_cnt[n] = (s_cnt < CAP) ? s_cnt : CAP;

    } else if (b < NN + 128) {
        // ---- theta = X @ W : 32-row x 128-col tile --------------------
        const int row0 = (b - NN) * 32;
        #pragma unroll
        for (int i = tid; i < 32 * NF; i += 256)
            Xs[i >> 7][i & 127] = X[(size_t)row0 * NF + i];
        __syncthreads();

        const int fp = tid & 63;          // float2 column
        const int rg = tid >> 6;          // row group 0..3
        const float2* __restrict__ W2 = reinterpret_cast<const float2*>(W);

        float acc[8][2];
        #pragma unroll
        for (int i = 0; i < 8; i++) { acc[i][0] = 0.f; acc[i][1] = 0.f; }

        #pragma unroll 4
        for (int k = 0; k < NF; k++) {
            float2 w = __ldg(&W2[k * 64 + fp]);
            #pragma unroll
            for (int i = 0; i < 8; i++) {
                float x = Xs[rg * 8 + i][k];
                acc[i][0] += x * w.x;
                acc[i][1] += x * w.y;
            }
        }
        #pragma unroll
        for (int i = 0; i < 8; i++) {
            int r = row0 + rg * 8 + i;
            *reinterpret_cast<float2*>(&g_theta[(size_t)r * NF + fp * 2]) =
                make_float2(acc[i][0], acc[i][1]);
        }

    } else {
        // ---- diagonal inverses ----------------------------------------
        int i = (b - NN - 128) * 256 + tid;
        if (i < NN) {
            g_inv_dv[i] = 1.0f / Dv[(size_t)i * (NN + 1)];
            g_inv_de[i] = 1.0f / De[(size_t)i * (NE + 1)];
        }
    }
}

// ---------------- SpMM gather core: warp per output row, float4 ----------
__device__ __forceinline__ float4 gather_row(const int* __restrict__ idx,
                                             int cnt,
                                             const float4* __restrict__ src,
                                             int lane) {
    float4 acc = make_float4(0.f, 0.f, 0.f, 0.f);
    int i = 0;
    for (; i + 8 <= cnt; i += 8) {
        int id[8];
        #pragma unroll
        for (int j = 0; j < 8; j++) id[j] = idx[i + j];
        float4 v[8];
        #pragma unroll
        for (int j = 0; j < 8; j++) v[j] = src[(size_t)id[j] * 32 + lane];
        #pragma unroll
        for (int j = 0; j < 8; j++) {
            acc.x += v[j].x; acc.y += v[j].y; acc.z += v[j].z; acc.w += v[j].w;
        }
    }
    for (; i < cnt; i++) {
        float4 v = src[(size_t)idx[i] * 32 + lane];
        acc.x += v.x; acc.y += v.y; acc.z += v.z; acc.w += v.w;
    }
    return acc;
}

// ---------------- K2: U[e] = inv_de[e] * sum_{n in col[e]} theta[n] ------
__global__ void __launch_bounds__(128) k_spmm1() {
    const int e    = blockIdx.x * 4 + (threadIdx.x >> 5);
    const int lane = threadIdx.x & 31;

    int cnt = g_col_cnt[e];
    if (cnt > CAP) cnt = CAP;
    float4 acc = gather_row(g_col_idx + (size_t)e * CAP, cnt,
                            reinterpret_cast<const float4*>(g_theta), lane);

    float s = g_inv_de[e];
    acc.x *= s; acc.y *= s; acc.z *= s; acc.w *= s;
    reinterpret_cast<float4*>(g_U)[(size_t)e * 32 + lane] = acc;

    if (lane == 0) g_col_cnt[e] = 0;      // leave zeroed for next launch
}

// ---------------- K3: Y[n] = inv_dv[n] * sum_{e in row[n]} U[e] ----------
__global__ void __launch_bounds__(128) k_spmm2(float* __restrict__ out) {
    const int n    = blockIdx.x * 4 + (threadIdx.x >> 5);
    const int lane = threadIdx.x & 31;

    int cnt = g_row_cnt[n];
    if (cnt > CAP) cnt = CAP;
    float4 acc = gather_row(g_row_idx + (size_t)n * CAP, cnt,
                            reinterpret_cast<const float4*>(g_U), lane);

    float s = g_inv_dv[n];
    acc.x *= s; acc.y *= s; acc.z *= s; acc.w *= s;
    reinterpret_cast<float4*>(out)[(size_t)n * 32 + lane] = acc;
}

// ---------------- launch --------------------------------------------------
extern "C" void kernel_launch(void* const* d_in, const int* in_sizes, int n_in,
                              void* d_out, int out_size) {
    const float* X  = (const float*)d_in[0];   // [4096,128]
    const float* H  = (const float*)d_in[1];   // [4096,4096]
    const float* Dv = (const float*)d_in[2];   // [4096,4096] diag
    const float* De = (const float*)d_in[3];   // [4096,4096] diag
    const float* W  = (const float*)d_in[4];   // [128,128]
    float* out = (float*)d_out;                // [4096,128]

    k_fused<<<NN + 128 + 16, 256>>>(X, W, H, Dv, De);
    k_spmm1<<<NE / 4, 128>>>();
    k_spmm2<<<NN / 4, 128>>>(out);
}

// round 9
// speedup vs baseline: 1.3511x; 1.3511x over previous
#include <cuda_runtime.h>

#define NN 4096      // nodes
#define NE 4096      // hyperedges
#define NF 128       // features
#define CAP 192      // per-list capacity (max degree ~58 expected)

// ---------------- scratch (static __device__, zero-initialized) ----------
__device__ float g_theta[NN * NF];        // X @ W            (2 MB, L2-resident)
__device__ float g_U[NE * NF];            // De^-1 H^T theta  (2 MB)
__device__ float g_inv_dv[NN];
__device__ float g_inv_de[NE];
__device__ int   g_col_cnt[NE];           // MUST be 0 at k_fused entry (zero at load;
__device__ int   g_row_cnt[NN];           //  spmm1/spmm2 re-zero after reading)
__device__ int   g_col_idx[NE * CAP];
__device__ int   g_row_idx[NN * CAP];

// ---------------- K1: fused init + theta + CSR/CSC build -----------------
// blockIdx roles:  [0, 1024)             -> build: 4 H rows per CTA (64 KB stream)
//                  [1024, 1024+128)      -> theta tile
//                  [1024+128, 1024+144)  -> diag inverses
#define BUILD_CTAS 1024
__global__ void __launch_bounds__(256) k_fused(const float* __restrict__ X,
                                               const float* __restrict__ W,
                                               const float* __restrict__ H,
                                               const float* __restrict__ Dv,
                                               const float* __restrict__ De) {
    __shared__ float Xs[32][NF];          // theta branch only

    const int b   = blockIdx.x;
    const int tid = threadIdx.x;

    if (b < BUILD_CTAS) {
        // ---- build: stream 4096 float4s (4 rows), bitmask then sparse append
        const float4* __restrict__ row4 =
            reinterpret_cast<const float4*>(H) + (size_t)b * 4096;

        unsigned long long mask = 0ull;
        #pragma unroll
        for (int half = 0; half < 2; half++) {
            float4 v[8];                              // 8 LDG.128 front-batched
            #pragma unroll
            for (int j = 0; j < 8; j++)
                v[j] = row4[tid + (half * 8 + j) * 256];
            #pragma unroll
            for (int j = 0; j < 8; j++) {
                unsigned m = (v[j].x != 0.f ? 1u : 0u)
                           | (v[j].y != 0.f ? 2u : 0u)
                           | (v[j].z != 0.f ? 4u : 0u)
                           | (v[j].w != 0.f ? 8u : 0u);
                mask |= (unsigned long long)m << ((half * 8 + j) * 4);
            }
        }

        // ~0.5 set bits per thread on average
        while (mask) {
            int bit = __ffsll((long long)mask) - 1;
            mask &= mask - 1;
            int kk  = bit >> 2;
            int j   = bit & 3;
            int off = kk * 256 + tid;                 // float4 index within chunk
            int n   = b * 4 + (off >> 10);
            int e   = ((off << 2) | j) & (NE - 1);

            int p = atomicAdd(&g_row_cnt[n], 1);      // spread over 4096 addrs
            if (p < CAP) g_row_idx[(size_t)n * CAP + p] = e;
            int q = atomicAdd(&g_col_cnt[e], 1);      // spread over 4096 addrs
            if (q < CAP) g_col_idx[(size_t)e * CAP + q] = n;
        }

    } else if (b < BUILD_CTAS + 128) {
        // ---- theta = X @ W : 32-row x 128-col tile --------------------
        const int row0 = (b - BUILD_CTAS) * 32;
        #pragma unroll
        for (int i = tid; i < 32 * NF; i += 256)
            Xs[i >> 7][i & 127] = X[(size_t)row0 * NF + i];
        __syncthreads();

        const int fp = tid & 63;          // float2 column
        const int rg = tid >> 6;          // row group 0..3
        const float2* __restrict__ W2 = reinterpret_cast<const float2*>(W);

        float acc[8][2];
        #pragma unroll
        for (int i = 0; i < 8; i++) { acc[i][0] = 0.f; acc[i][1] = 0.f; }

        #pragma unroll 4
        for (int k = 0; k < NF; k++) {
            float2 w = __ldg(&W2[k * 64 + fp]);
            #pragma unroll
            for (int i = 0; i < 8; i++) {
                float x = Xs[rg * 8 + i][k];
                acc[i][0] += x * w.x;
                acc[i][1] += x * w.y;
            }
        }
        #pragma unroll
        for (int i = 0; i < 8; i++) {
            int r = row0 + rg * 8 + i;
            *reinterpret_cast<float2*>(&g_theta[(size_t)r * NF + fp * 2]) =
                make_float2(acc[i][0], acc[i][1]);
        }

    } else {
        // ---- diagonal inverses ----------------------------------------
        int i = (b - BUILD_CTAS - 128) * 256 + tid;
        if (i < NN) {
            g_inv_dv[i] = 1.0f / Dv[(size_t)i * (NN + 1)];
            g_inv_de[i] = 1.0f / De[(size_t)i * (NE + 1)];
        }
    }
}

// ---------------- SpMM gather core: warp per output row, float4 ----------
__device__ __forceinline__ float4 gather_row(const int* __restrict__ idx,
                                             int cnt,
                                             const float4* __restrict__ src,
                                             int lane) {
    float4 acc = make_float4(0.f, 0.f, 0.f, 0.f);
    int i = 0;
    for (; i + 8 <= cnt; i += 8) {
        int id[8];
        #pragma unroll
        for (int j = 0; j < 8; j++) id[j] = idx[i + j];
        float4 v[8];
        #pragma unroll
        for (int j = 0; j < 8; j++) v[j] = src[(size_t)id[j] * 32 + lane];
        #pragma unroll
        for (int j = 0; j < 8; j++) {
            acc.x += v[j].x; acc.y += v[j].y; acc.z += v[j].z; acc.w += v[j].w;
        }
    }
    for (; i < cnt; i++) {
        float4 v = src[(size_t)idx[i] * 32 + lane];
        acc.x += v.x; acc.y += v.y; acc.z += v.z; acc.w += v.w;
    }
    return acc;
}

// ---------------- K2: U[e] = inv_de[e] * sum_{n in col[e]} theta[n] ------
__global__ void __launch_bounds__(128) k_spmm1() {
    const int e    = blockIdx.x * 4 + (threadIdx.x >> 5);
    const int lane = threadIdx.x & 31;

    int cnt = g_col_cnt[e];
    if (cnt > CAP) cnt = CAP;
    float4 acc = gather_row(g_col_idx + (size_t)e * CAP, cnt,
                            reinterpret_cast<const float4*>(g_theta), lane);

    float s = g_inv_de[e];
    acc.x *= s; acc.y *= s; acc.z *= s; acc.w *= s;
    reinterpret_cast<float4*>(g_U)[(size_t)e * 32 + lane] = acc;

    if (lane == 0) g_col_cnt[e] = 0;      // leave zeroed for next launch
}

// ---------------- K3: Y[n] = inv_dv[n] * sum_{e in row[n]} U[e] ----------
__global__ void __launch_bounds__(128) k_spmm2(float* __restrict__ out) {
    const int n    = blockIdx.x * 4 + (threadIdx.x >> 5);
    const int lane = threadIdx.x & 31;

    int cnt = g_row_cnt[n];
    if (cnt > CAP) cnt = CAP;
    float4 acc = gather_row(g_row_idx + (size_t)n * CAP, cnt,
                            reinterpret_cast<const float4*>(g_U), lane);

    float s = g_inv_dv[n];
    acc.x *= s; acc.y *= s; acc.z *= s; acc.w *= s;
    reinterpret_cast<float4*>(out)[(size_t)n * 32 + lane] = acc;

    if (lane == 0) g_row_cnt[n] = 0;      // leave zeroed for next launch
}

// ---------------- launch --------------------------------------------------
extern "C" void kernel_launch(void* const* d_in, const int* in_sizes, int n_in,
                              void* d_out, int out_size) {
    const float* X  = (const float*)d_in[0];   // [4096,128]
    const float* H  = (const float*)d_in[1];   // [4096,4096]
    const float* Dv = (const float*)d_in[2];   // [4096,4096] diag
    const float* De = (const float*)d_in[3];   // [4096,4096] diag
    const float* W  = (const float*)d_in[4];   // [128,128]
    float* out = (float*)d_out;                // [4096,128]

    k_fused<<<BUILD_CTAS + 128 + 16, 256>>>(X, W, H, Dv, De);
    k_spmm1<<<NE / 4, 128>>>();
    k_spmm2<<<NN / 4, 128>>>(out);
}